// round 7
// baseline (speedup 1.0000x reference)
#include <cuda_runtime.h>
#include <cuda_fp16.h>
#include <stdint.h>
#include <math.h>

#define NT   256
#define TILE 128

// weight blob layout: n-major [64 rows][Kpad halves], hi and lo arrays
#define KP64  144                 // bytes per row, K=64  (72 halves)
#define KP128 272                 // bytes per row, K=128 (136 halves)
#define SZ64  (64*KP64)           // 9216
#define SZ128 (64*KP128)          // 17408

#define NW1H 0
#define NW1L (NW1H+SZ64)
#define NW2H (NW1L+SZ64)
#define NW2L (NW2H+SZ64)
#define AW1H (NW2L+SZ64)
#define AW1L (AW1H+SZ128)
#define AW2H (AW1L+SZ128)
#define AW2L (AW2H+SZ64)
#define OW1H (AW2L+SZ64)
#define OW1L (OW1H+SZ128)
#define OW2H (OW1L+SZ128)
#define OW2L (OW2H+SZ64)
#define WBYTES (OW2L+SZ64)        // 143360

#define BIAS_OFF WBYTES           // 1536 B
#define TV_OFF   (BIAS_OFF + 1536)
#define ACT_OFF  (TV_OFF + 256)   // 145152
// activation lo buffers: 128 rows x 144 B, 4 buffers (S0,S1,S2,H)
#define ABUF     18432
#define SMEM_REQ (ACT_OFF + 4*ABUF)   // 218880

__device__ __align__(16) unsigned char g_wblob[WBYTES];

// ---------------- helpers ----------------
__device__ __forceinline__ uint32_t smem_u32(const void* p) {
    uint32_t a;
    asm("{ .reg .u64 t; cvta.to.shared.u64 t, %1; cvt.u32.u64 %0, t; }" : "=r"(a) : "l"(p));
    return a;
}

__device__ __forceinline__ void split2(float x0, float x1, uint32_t& hi, uint32_t& lo) {
    __half h0 = __float2half_rn(x0), h1 = __float2half_rn(x1);
    __half l0 = __float2half_rn(x0 - __half2float(h0));
    __half l1 = __float2half_rn(x1 - __half2float(h1));
    __half2 H = __halves2half2(h0, h1), L = __halves2half2(l0, l1);
    hi = *reinterpret_cast<uint32_t*>(&H);
    lo = *reinterpret_cast<uint32_t*>(&L);
}

#define MMA(D, a0, a1, a2, a3, b0, b1) \
    asm volatile("mma.sync.aligned.m16n8k16.row.col.f32.f16.f16.f32 " \
        "{%0,%1,%2,%3},{%4,%5,%6,%7},{%8,%9},{%0,%1,%2,%3};" \
        : "+f"((D)[0]), "+f"((D)[1]), "+f"((D)[2]), "+f"((D)[3]) \
        : "r"(a0), "r"(a1), "r"(a2), "r"(a3), "r"(b0), "r"(b1))

#define LDSM4(r0, r1, r2, r3, a) \
    asm volatile("ldmatrix.sync.aligned.m8n8.x4.shared.b16 {%0,%1,%2,%3}, [%4];" \
        : "=r"(r0), "=r"(r1), "=r"(r2), "=r"(r3) : "r"(a))

#define STS32(a, v) asm volatile("st.shared.b32 [%0], %1;" :: "r"(a), "r"(v) : "memory")

struct Slot { uint32_t h[16]; };   // activation hi halves only (lo lives in smem)
struct Frag {                      // one k-tile's operands: weights hi/lo x 4 np, act lo
    uint32_t h[4][4];
    uint32_t l[4][4];
    uint32_t a[4];
};

// ---------------- weight conversion ----------------
__global__ void convert_weights(const float* __restrict__ nW1, const float* __restrict__ nW2,
                                const float* __restrict__ aW1, const float* __restrict__ aW2,
                                const float* __restrict__ oW1, const float* __restrict__ oW2) {
    int i = blockIdx.x * blockDim.x + threadIdx.x;
    if (i >= 32768) return;
    int idx = i; const float* src; int hb, lb, kp;
    if (idx < 4096)       { src = nW1; hb = NW1H; lb = NW1L; kp = KP64; }
    else if (idx < 8192)  { idx -= 4096;  src = nW2; hb = NW2H; lb = NW2L; kp = KP64; }
    else if (idx < 16384) { idx -= 8192;  src = aW1; hb = AW1H; lb = AW1L; kp = KP128; }
    else if (idx < 20480) { idx -= 16384; src = aW2; hb = AW2H; lb = AW2L; kp = KP64; }
    else if (idx < 28672) { idx -= 20480; src = oW1; hb = OW1H; lb = OW1L; kp = KP128; }
    else                  { idx -= 28672; src = oW2; hb = OW2H; lb = OW2L; kp = KP64; }
    int k = idx >> 6, n = idx & 63;
    float w = src[idx];
    __half h = __float2half_rn(w);
    __half l = __float2half_rn(w - __half2float(h));
    *(__half*)(g_wblob + hb + n * kp + k * 2) = h;
    *(__half*)(g_wblob + lb + n * kp + k * 2) = l;
}

// ---------------- core compute ----------------
__device__ __forceinline__ void zeroD(float (&D)[8][4]) {
#pragma unroll
    for (int n = 0; n < 8; n++)
#pragma unroll
        for (int i = 0; i < 4; i++) D[n][i] = 0.f;
}

// load all operands for one k-tile (9 x LDSM4)
__device__ __forceinline__ void load_kt(Frag& F, uint32_t alo,
                                        uint32_t baseH, uint32_t baseL,
                                        int kpB, int k0, int kt, int bn, int bk) {
    int kbyte = (k0 + kt * 16 + bk) * 2;
#pragma unroll
    for (int np = 0; np < 4; np++) {
        uint32_t ro = (uint32_t)((np * 16 + bn) * kpB + kbyte);
        LDSM4(F.h[np][0], F.h[np][1], F.h[np][2], F.h[np][3], baseH + ro);
        LDSM4(F.l[np][0], F.l[np][1], F.l[np][2], F.l[np][3], baseL + ro);
    }
    LDSM4(F.a[0], F.a[1], F.a[2], F.a[3], alo + (uint32_t)(kt * 32));
}

// 24 MMAs for one k-tile, 3 passes x 4 np -> 8-accumulator interleave
__device__ __forceinline__ void mma_kt(float (&D)[8][4], const Slot& A, const Frag& F, int kt) {
    const uint32_t a0 = A.h[kt*4], a1 = A.h[kt*4+1], a2 = A.h[kt*4+2], a3 = A.h[kt*4+3];
#pragma unroll
    for (int np = 0; np < 4; np++) {
        MMA(D[2*np],   a0, a1, a2, a3, F.h[np][0], F.h[np][1]);
        MMA(D[2*np+1], a0, a1, a2, a3, F.h[np][2], F.h[np][3]);
    }
#pragma unroll
    for (int np = 0; np < 4; np++) {
        MMA(D[2*np],   a0, a1, a2, a3, F.l[np][0], F.l[np][1]);
        MMA(D[2*np+1], a0, a1, a2, a3, F.l[np][2], F.l[np][3]);
    }
#pragma unroll
    for (int np = 0; np < 4; np++) {
        MMA(D[2*np],   F.a[0], F.a[1], F.a[2], F.a[3], F.h[np][0], F.h[np][1]);
        MMA(D[2*np+1], F.a[0], F.a[1], F.a[2], F.a[3], F.h[np][2], F.h[np][3]);
    }
}

// one K=64 chunk, software-pipelined at k-tile granularity (double-buffered frags)
__device__ __forceinline__ void chunk64(float (&D)[8][4], const Slot& A, uint32_t alo,
                                        uint32_t baseH, uint32_t baseL, int kpB, int k0,
                                        int bn, int bk) {
    Frag F0, F1;
    load_kt(F0, alo, baseH, baseL, kpB, k0, 0, bn, bk);
    load_kt(F1, alo, baseH, baseL, kpB, k0, 1, bn, bk);
    mma_kt(D, A, F0, 0);
    load_kt(F0, alo, baseH, baseL, kpB, k0, 2, bn, bk);
    mma_kt(D, A, F1, 1);
    load_kt(F1, alo, baseH, baseL, kpB, k0, 3, bn, bk);
    mma_kt(D, A, F0, 2);
    mma_kt(D, A, F1, 3);
}

// D + bias (+lrelu) -> hi into regs (A-frag layout), lo into smem buffer
__device__ __forceinline__ void epi_slot(float (&D)[8][4], const float* __restrict__ bias,
                                         bool lrelu, Slot& S, uint32_t loW, int lane) {
    int c0 = 2 * (lane & 3);
#pragma unroll
    for (int nt = 0; nt < 8; nt++) {
        float b0 = bias[nt*8 + c0], b1 = bias[nt*8 + c0 + 1];
        float x0 = D[nt][0] + b0, x1 = D[nt][1] + b1;
        float x2 = D[nt][2] + b0, x3 = D[nt][3] + b1;
        if (lrelu) {
            x0 = x0 > 0.f ? x0 : 0.01f * x0;
            x1 = x1 > 0.f ? x1 : 0.01f * x1;
            x2 = x2 > 0.f ? x2 : 0.01f * x2;
            x3 = x3 > 0.f ? x3 : 0.01f * x3;
        }
        int r = (nt >> 1) * 4 + (nt & 1) * 2;
        uint32_t lo01, lo23;
        split2(x0, x1, S.h[r],     lo01);
        split2(x2, x3, S.h[r + 1], lo23);
        STS32(loW + (uint32_t)(nt * 16),        lo01);   // row g,   col nt*8+c0
        STS32(loW + (uint32_t)(nt * 16 + 1152), lo23);   // row g+8
    }
    __syncwarp();
}

// two-layer MLP: leaves layer-2 raw accumulators in D (bias not applied)
__device__ __forceinline__ void mlp(float (&D)[8][4], Slot& H,
                                    const Slot& in1, const Slot* in2,
                                    uint32_t alo1, uint32_t alo2,
                                    uint32_t aloH, uint32_t loWH, uint32_t sb,
                                    uint32_t w1h, uint32_t w1l, int kp1, const float* b1,
                                    uint32_t w2h, uint32_t w2l,
                                    int bn, int bk, int lane) {
    zeroD(D);
    chunk64(D, in1, alo1, sb + w1h, sb + w1l, kp1, 0, bn, bk);
    if (in2) chunk64(D, *in2, alo2, sb + w1h, sb + w1l, kp1, 64, bn, bk);
    epi_slot(D, b1, true, H, loWH, lane);
    zeroD(D);
    chunk64(D, H, aloH, sb + w2h, sb + w2l, KP64, 0, bn, bk);
}

// gather embedding rows (r1, r2 = r1+8): hi into regs, lo into smem buffer
__device__ __forceinline__ void gather(Slot& S, uint32_t loW, const float* __restrict__ item,
                                       int i1, int i2, int lane) {
    const float* p1 = item + (size_t)i1 * 64 + 2 * (lane & 3);
    const float* p2 = item + (size_t)i2 * 64 + 2 * (lane & 3);
#pragma unroll
    for (int j = 0; j < 4; j++) {
        float2 a = *(const float2*)(p1 + j * 16);
        float2 b = *(const float2*)(p2 + j * 16);
        float2 c = *(const float2*)(p1 + j * 16 + 8);
        float2 d = *(const float2*)(p2 + j * 16 + 8);
        uint32_t lo;
        split2(a.x, a.y, S.h[j*4+0], lo); STS32(loW + (uint32_t)(j*32),            lo);
        split2(b.x, b.y, S.h[j*4+1], lo); STS32(loW + (uint32_t)(j*32 + 1152),     lo);
        split2(c.x, c.y, S.h[j*4+2], lo); STS32(loW + (uint32_t)(j*32 + 16),       lo);
        split2(d.x, d.y, S.h[j*4+3], lo); STS32(loW + (uint32_t)(j*32 + 1152+16),  lo);
    }
    __syncwarp();
}

// cosine-similarity epilogue on raw layer-2 accumulators
__device__ __forceinline__ void final_epi(float (&D)[8][4], const float* __restrict__ bias,
                                          const float* __restrict__ tv, float tnorm,
                                          float* __restrict__ outp, int r1, int lane) {
    int c0 = 2 * (lane & 3);
    float n1 = 0.f, s1 = 0.f, n2 = 0.f, s2 = 0.f;
#pragma unroll
    for (int nt = 0; nt < 8; nt++) {
        float b0 = bias[nt*8 + c0], b1 = bias[nt*8 + c0 + 1];
        float t0 = tv[nt*8 + c0],  t1 = tv[nt*8 + c0 + 1];
        float x0 = D[nt][0] + b0, x1 = D[nt][1] + b1;
        float x2 = D[nt][2] + b0, x3 = D[nt][3] + b1;
        n1 = fmaf(x0, t0, fmaf(x1, t1, n1));  s1 = fmaf(x0, x0, fmaf(x1, x1, s1));
        n2 = fmaf(x2, t0, fmaf(x3, t1, n2));  s2 = fmaf(x2, x2, fmaf(x3, x3, s2));
    }
    n1 += __shfl_xor_sync(~0u, n1, 1); n1 += __shfl_xor_sync(~0u, n1, 2);
    s1 += __shfl_xor_sync(~0u, s1, 1); s1 += __shfl_xor_sync(~0u, s1, 2);
    n2 += __shfl_xor_sync(~0u, n2, 1); n2 += __shfl_xor_sync(~0u, n2, 2);
    s2 += __shfl_xor_sync(~0u, s2, 1); s2 += __shfl_xor_sync(~0u, s2, 2);
    if ((lane & 3) == 0) {
        float dn = fmaxf(tnorm, 1e-8f);
        outp[r1]     = n1 / (fmaxf(sqrtf(s1), 1e-8f) * dn) * 10.0f;
        outp[r1 + 8] = n2 / (fmaxf(sqrtf(s2), 1e-8f) * dn) * 10.0f;
    }
}

// ---------------- main kernel ----------------
__global__ void __launch_bounds__(NT, 1) logicnet_mma(
    const int* __restrict__ seq, const int* __restrict__ post, const int* __restrict__ negt,
    const float* __restrict__ item, const float* __restrict__ tvec,
    const float* __restrict__ nb1, const float* __restrict__ nb2,
    const float* __restrict__ ab1, const float* __restrict__ ab2,
    const float* __restrict__ ob1, const float* __restrict__ ob2,
    float* __restrict__ out, int batch)
{
    extern __shared__ unsigned char sm[];
    {   // stage pre-split, pre-laid-out weights
        const float4* s4 = (const float4*)g_wblob;
        float4* d4 = (float4*)sm;
        for (int i = threadIdx.x; i < WBYTES / 16; i += NT) d4[i] = s4[i];
    }
    float* bias = (float*)(sm + BIAS_OFF);
    if (threadIdx.x < 64) {
        int t = threadIdx.x;
        bias[t]       = nb1[t]; bias[64 + t]  = nb2[t];
        bias[128 + t] = ab1[t]; bias[192 + t] = ab2[t];
        bias[256 + t] = ob1[t]; bias[320 + t] = ob2[t];
        ((float*)(sm + TV_OFF))[t] = tvec[t];
    }
    __syncthreads();

    const uint32_t sb = smem_u32(sm);
    const float* tv = (const float*)(sm + TV_OFF);
    const int lane = threadIdx.x & 31;
    const int wid  = threadIdx.x >> 5;
    const int bn = (lane & 7) + ((lane >> 4) << 3);
    const int bk = ((lane >> 3) & 1) * 8;
    const int r1 = blockIdx.x * TILE + wid * 16 + (lane >> 2);
    const int r2 = r1 + 8;

    // per-thread activation-lo smem addressing (warp-private 16 rows, 144B stride)
    const uint32_t actRd = sb + ACT_OFF + (uint32_t)((wid*16 + (lane & 15)) * 144 + ((lane >> 4) << 4));
    const uint32_t actWr = sb + ACT_OFF + (uint32_t)((wid*16 + (lane >> 2)) * 144 + ((lane & 3) << 2));
    const uint32_t aloS0 = actRd,            aloS1 = actRd + ABUF;
    const uint32_t aloS2 = actRd + 2*ABUF,   aloH  = actRd + 3*ABUF;
    const uint32_t loWS0 = actWr,            loWS1 = actWr + ABUF;
    const uint32_t loWS2 = actWr + 2*ABUF,   loWH  = actWr + 3*ABUF;

    float tn = tv[lane] * tv[lane] + tv[lane + 32] * tv[lane + 32];
#pragma unroll
    for (int m = 16; m; m >>= 1) tn += __shfl_xor_sync(~0u, tn, m);
    const float tnorm = sqrtf(tn);

    Slot S0, S1, S2, H;
    float D[8][4];

    gather(S0, loWS0, item, seq[r1 * 5 + 0], seq[r2 * 5 + 0], lane);   // e0
    gather(S1, loWS1, item, seq[r1 * 5 + 1], seq[r2 * 5 + 1], lane);   // e1
    // n1 = NOT(e1) -> S1
    mlp(D, H, S1, nullptr, aloS1, 0,     aloH, loWH, sb, NW1H, NW1L, KP64,  bias + 0,   NW2H, NW2L, bn, bk, lane);
    epi_slot(D, bias + 64, false, S1, loWS1, lane);
    // i5 = AND(e0, n1) -> S0
    mlp(D, H, S0, &S1,     aloS0, aloS1, aloH, loWH, sb, AW1H, AW1L, KP128, bias + 128, AW2H, AW2L, bn, bk, lane);
    epi_slot(D, bias + 192, false, S0, loWS0, lane);
    gather(S1, loWS1, item, seq[r1 * 5 + 2], seq[r2 * 5 + 2], lane);   // e2
    gather(S2, loWS2, item, seq[r1 * 5 + 3], seq[r2 * 5 + 3], lane);   // e3
    // i6 = OR(e2, e3) -> S1
    mlp(D, H, S1, &S2,     aloS1, aloS2, aloH, loWH, sb, OW1H, OW1L, KP128, bias + 256, OW2H, OW2L, bn, bk, lane);
    epi_slot(D, bias + 320, false, S1, loWS1, lane);
    // i7 = AND(i5, i6) -> S0
    mlp(D, H, S0, &S1,     aloS0, aloS1, aloH, loWH, sb, AW1H, AW1L, KP128, bias + 128, AW2H, AW2L, bn, bk, lane);
    epi_slot(D, bias + 192, false, S0, loWS0, lane);
    // n7 = NOT(i7) -> S1
    mlp(D, H, S0, nullptr, aloS0, 0,     aloH, loWH, sb, NW1H, NW1L, KP64,  bias + 0,   NW2H, NW2L, bn, bk, lane);
    epi_slot(D, bias + 64, false, S1, loWS1, lane);
    gather(S2, loWS2, item, seq[r1 * 5 + 4], seq[r2 * 5 + 4], lane);   // e4
    // i8 = OR(n7, e4) -> S0
    mlp(D, H, S1, &S2,     aloS1, aloS2, aloH, loWH, sb, OW1H, OW1L, KP128, bias + 256, OW2H, OW2L, bn, bk, lane);
    epi_slot(D, bias + 320, false, S0, loWS0, lane);
    // enc_not = NOT(i8) -> S1
    mlp(D, H, S0, nullptr, aloS0, 0,     aloH, loWH, sb, NW1H, NW1L, KP64,  bias + 0,   NW2H, NW2L, bn, bk, lane);
    epi_slot(D, bias + 64, false, S1, loWS1, lane);
    gather(S2, loWS2, item, post[r1], post[r2], lane);                 // pos_e
    // encoded_pos = OR(enc_not, pos_e)
    mlp(D, H, S1, &S2,     aloS1, aloS2, aloH, loWH, sb, OW1H, OW1L, KP128, bias + 256, OW2H, OW2L, bn, bk, lane);
    final_epi(D, bias + 320, tv, tnorm, out, r1, lane);
    gather(S2, loWS2, item, negt[r1], negt[r2], lane);                 // neg_e
    // encoded_neg = OR(enc_not, neg_e)
    mlp(D, H, S1, &S2,     aloS1, aloS2, aloH, loWH, sb, OW1H, OW1L, KP128, bias + 256, OW2H, OW2L, bn, bk, lane);
    final_epi(D, bias + 320, tv, tnorm, out + batch, r1, lane);
}

extern "C" void kernel_launch(void* const* d_in, const int* in_sizes, int n_in,
                              void* d_out, int out_size) {
    const int*   seq   = (const int*)  d_in[0];
    const int*   pos_t = (const int*)  d_in[1];
    const int*   neg_t = (const int*)  d_in[2];
    const float* item  = (const float*)d_in[3];
    const float* tvec  = (const float*)d_in[4];
    const float* nW1 = (const float*)d_in[5];
    const float* nb1 = (const float*)d_in[6];
    const float* nW2 = (const float*)d_in[7];
    const float* nb2 = (const float*)d_in[8];
    const float* aW1 = (const float*)d_in[9];
    const float* ab1 = (const float*)d_in[10];
    const float* aW2 = (const float*)d_in[11];
    const float* ab2 = (const float*)d_in[12];
    const float* oW1 = (const float*)d_in[13];
    const float* ob1 = (const float*)d_in[14];
    const float* oW2 = (const float*)d_in[15];
    const float* ob2 = (const float*)d_in[16];
    float* out = (float*)d_out;

    int batch = in_sizes[1];
    convert_weights<<<128, 256>>>(nW1, nW2, aW1, aW2, oW1, oW2);

    cudaFuncSetAttribute(logicnet_mma, cudaFuncAttributeMaxDynamicSharedMemorySize, SMEM_REQ);
    logicnet_mma<<<batch / TILE, NT, SMEM_REQ>>>(
        seq, pos_t, neg_t, item, tvec,
        nb1, nb2, ab1, ab2, ob1, ob2, out, batch);
}

// round 8
// speedup vs baseline: 1.0306x; 1.0306x over previous
#include <cuda_runtime.h>
#include <cuda_fp16.h>
#include <stdint.h>
#include <math.h>

#define NT   384
#define TILE 192

// packed, XOR-swizzled weight tiles: n-major, row stride = K*2 bytes
#define RS64  128
#define RS128 256
#define SZ64  (64*RS64)     // 8192
#define SZ128 (64*RS128)    // 16384

#define NW1H 0
#define NW1L 8192
#define NW2H 16384
#define NW2L 24576
#define AW1H 32768
#define AW1L 49152
#define AW2H 65536
#define AW2L 73728
#define OW1H 81920
#define OW1L 98304
#define OW2H 114688
#define OW2L 122880
#define WBYTES 131072

#define BIAS_OFF WBYTES            // 1536 B (6 x 64 floats)
#define TV_OFF   (BIAS_OFF + 1536)
#define ACT_OFF  (TV_OFF + 256)    // 132864
#define ABUF     (TILE*128)        // 24576 per lo-buffer (swizzled 128B rows)
#define SMEM_REQ (ACT_OFF + 3*ABUF)   // 206592

__device__ __align__(16) unsigned char g_wblob[WBYTES];

// ---------------- helpers ----------------
__device__ __forceinline__ uint32_t smem_u32(const void* p) {
    uint32_t a;
    asm("{ .reg .u64 t; cvta.to.shared.u64 t, %1; cvt.u32.u64 %0, t; }" : "=r"(a) : "l"(p));
    return a;
}

__device__ __forceinline__ void split2(float x0, float x1, uint32_t& hi, uint32_t& lo) {
    __half h0 = __float2half_rn(x0), h1 = __float2half_rn(x1);
    __half l0 = __float2half_rn(x0 - __half2float(h0));
    __half l1 = __float2half_rn(x1 - __half2float(h1));
    __half2 H = __halves2half2(h0, h1), L = __halves2half2(l0, l1);
    hi = *reinterpret_cast<uint32_t*>(&H);
    lo = *reinterpret_cast<uint32_t*>(&L);
}

#define MMA(D, a0, a1, a2, a3, b0, b1) \
    asm volatile("mma.sync.aligned.m16n8k16.row.col.f32.f16.f16.f32 " \
        "{%0,%1,%2,%3},{%4,%5,%6,%7},{%8,%9},{%0,%1,%2,%3};" \
        : "+f"((D)[0]), "+f"((D)[1]), "+f"((D)[2]), "+f"((D)[3]) \
        : "r"(a0), "r"(a1), "r"(a2), "r"(a3), "r"(b0), "r"(b1))

#define LDSM4(r0, r1, r2, r3, a) \
    asm volatile("ldmatrix.sync.aligned.m8n8.x4.shared.b16 {%0,%1,%2,%3}, [%4];" \
        : "=r"(r0), "=r"(r1), "=r"(r2), "=r"(r3) : "r"(a))

#define STS32(a, v) asm volatile("st.shared.b32 [%0], %1;" :: "r"(a), "r"(v) : "memory")

struct Slot { uint32_t h[16]; };   // activation hi halves (lo lives in smem)

// ---------------- weight conversion: fp32 -> fp16 hi/lo, packed swizzled ----------------
__global__ void convert_weights(const float* __restrict__ nW1, const float* __restrict__ nW2,
                                const float* __restrict__ aW1, const float* __restrict__ aW2,
                                const float* __restrict__ oW1, const float* __restrict__ oW2) {
    int i = blockIdx.x * blockDim.x + threadIdx.x;
    if (i >= 32768) return;
    int idx = i; const float* src; int hb, lb, rs;
    if (idx < 4096)       { src = nW1; hb = NW1H; lb = NW1L; rs = RS64; }
    else if (idx < 8192)  { idx -= 4096;  src = nW2; hb = NW2H; lb = NW2L; rs = RS64; }
    else if (idx < 16384) { idx -= 8192;  src = aW1; hb = AW1H; lb = AW1L; rs = RS128; }
    else if (idx < 20480) { idx -= 16384; src = aW2; hb = AW2H; lb = AW2L; rs = RS64; }
    else if (idx < 28672) { idx -= 20480; src = oW1; hb = OW1H; lb = OW1L; rs = RS128; }
    else                  { idx -= 28672; src = oW2; hb = OW2H; lb = OW2L; rs = RS64; }
    int k = idx >> 6, n = idx & 63;          // source row-major [K][64]
    float w = src[idx];
    __half h = __float2half_rn(w);
    __half l = __float2half_rn(w - __half2float(h));
    // swizzled offset: row n, 16B-chunk (k>>3) XOR (n&7), byte (k&7)*2
    int off = n * rs + (((k >> 3) ^ (n & 7)) << 4) + (k & 7) * 2;
    *(__half*)(g_wblob + hb + off) = h;
    *(__half*)(g_wblob + lb + off) = l;
}

// ---------------- core compute ----------------
__device__ __forceinline__ void zeroD(float (&D)[8][4]) {
#pragma unroll
    for (int n = 0; n < 8; n++)
#pragma unroll
        for (int i = 0; i < 4; i++) D[n][i] = 0.f;
}

// one K=64 chunk: D += Ah*Wh + Al*Wh + Ah*Wl
// kc0: starting 16B-chunk index (0 for k0=0, 8 for k0=64)
__device__ __forceinline__ void chunk64(float (&D)[8][4], const Slot& A, uint32_t aRd,
                                        uint32_t baseH, uint32_t baseL, int rs, int kc0,
                                        int bn, int hk8, int hk16, int rn7) {
#pragma unroll
    for (int kt = 0; kt < 4; kt++) {
        const uint32_t a0 = A.h[kt*4], a1 = A.h[kt*4+1], a2 = A.h[kt*4+2], a3 = A.h[kt*4+3];
        uint32_t xw = (uint32_t)((((kc0 + kt*2 + hk8) ^ rn7)) << 4);
        uint32_t xa = (uint32_t)((((kt*2 + hk16) ^ rn7)) << 4);
        uint32_t al0, al1, al2, al3;
        LDSM4(al0, al1, al2, al3, aRd + xa);
        uint32_t h[4][4];
#pragma unroll
        for (int np = 0; np < 4; np++) {
            uint32_t ro = (uint32_t)((np*16 + bn) * rs) + xw;
            LDSM4(h[np][0], h[np][1], h[np][2], h[np][3], baseH + ro);
        }
#pragma unroll
        for (int np = 0; np < 4; np++) {
            MMA(D[2*np],   a0, a1, a2, a3, h[np][0], h[np][1]);
            MMA(D[2*np+1], a0, a1, a2, a3, h[np][2], h[np][3]);
        }
#pragma unroll
        for (int np = 0; np < 4; np++) {
            MMA(D[2*np],   al0, al1, al2, al3, h[np][0], h[np][1]);
            MMA(D[2*np+1], al0, al1, al2, al3, h[np][2], h[np][3]);
        }
        uint32_t l[4][4];
#pragma unroll
        for (int np = 0; np < 4; np++) {
            uint32_t ro = (uint32_t)((np*16 + bn) * rs) + xw;
            LDSM4(l[np][0], l[np][1], l[np][2], l[np][3], baseL + ro);
        }
#pragma unroll
        for (int np = 0; np < 4; np++) {
            MMA(D[2*np],   a0, a1, a2, a3, l[np][0], l[np][1]);
            MMA(D[2*np+1], a0, a1, a2, a3, l[np][2], l[np][3]);
        }
    }
}

// D + bias (+lrelu) -> hi into regs (A-frag layout), lo into swizzled smem buffer
__device__ __forceinline__ void epi_slot(float (&D)[8][4], const float* __restrict__ bias,
                                         bool lrelu, Slot& S, uint32_t wAddr, int g7, int lane) {
    int c0 = 2 * (lane & 3);
#pragma unroll
    for (int nt = 0; nt < 8; nt++) {
        float b0 = bias[nt*8 + c0], b1 = bias[nt*8 + c0 + 1];
        float x0 = D[nt][0] + b0, x1 = D[nt][1] + b1;
        float x2 = D[nt][2] + b0, x3 = D[nt][3] + b1;
        if (lrelu) {
            x0 = x0 > 0.f ? x0 : 0.01f * x0;
            x1 = x1 > 0.f ? x1 : 0.01f * x1;
            x2 = x2 > 0.f ? x2 : 0.01f * x2;
            x3 = x3 > 0.f ? x3 : 0.01f * x3;
        }
        int r = (nt >> 1) * 4 + (nt & 1) * 2;
        uint32_t lo01, lo23;
        split2(x0, x1, S.h[r],     lo01);
        split2(x2, x3, S.h[r + 1], lo23);
        uint32_t a = wAddr + (uint32_t)(((nt ^ g7)) << 4);
        STS32(a,        lo01);   // row g
        STS32(a + 1024, lo23);   // row g+8
    }
    __syncwarp();
}

// two-layer MLP: leaves layer-2 raw accumulators in D (bias not applied)
// H-lo shares the DST buffer (hWr/hRd point at the dst slot's lo buffer)
__device__ __forceinline__ void mlp(float (&D)[8][4], Slot& H,
                                    const Slot& in1, const Slot* in2,
                                    uint32_t a1Rd, uint32_t a2Rd,
                                    uint32_t hRd, uint32_t hWr, uint32_t sb,
                                    uint32_t w1h, uint32_t w1l, int rs1, const float* b1,
                                    uint32_t w2h, uint32_t w2l,
                                    int bn, int hk8, int hk16, int rn7, int g7, int lane) {
    zeroD(D);
    chunk64(D, in1, a1Rd, sb + w1h, sb + w1l, rs1, 0, bn, hk8, hk16, rn7);
    if (in2) chunk64(D, *in2, a2Rd, sb + w1h, sb + w1l, rs1, 8, bn, hk8, hk16, rn7);
    epi_slot(D, b1, true, H, hWr, g7, lane);
    zeroD(D);
    chunk64(D, H, hRd, sb + w2h, sb + w2l, RS64, 0, bn, hk8, hk16, rn7);
}

// gather embedding rows (r1, r2 = r1+8): hi into regs, lo into swizzled smem buffer
__device__ __forceinline__ void gather(Slot& S, uint32_t wAddr, int g7,
                                       const float* __restrict__ item,
                                       int i1, int i2, int lane) {
    const float* p1 = item + (size_t)i1 * 64 + 2 * (lane & 3);
    const float* p2 = item + (size_t)i2 * 64 + 2 * (lane & 3);
#pragma unroll
    for (int j = 0; j < 4; j++) {
        float2 a = *(const float2*)(p1 + j * 16);
        float2 b = *(const float2*)(p2 + j * 16);
        float2 c = *(const float2*)(p1 + j * 16 + 8);
        float2 d = *(const float2*)(p2 + j * 16 + 8);
        uint32_t lo;
        uint32_t a0 = wAddr + (uint32_t)((((2*j)     ^ g7)) << 4);
        uint32_t a1 = wAddr + (uint32_t)((((2*j + 1) ^ g7)) << 4);
        split2(a.x, a.y, S.h[j*4+0], lo); STS32(a0,        lo);
        split2(b.x, b.y, S.h[j*4+1], lo); STS32(a0 + 1024, lo);
        split2(c.x, c.y, S.h[j*4+2], lo); STS32(a1,        lo);
        split2(d.x, d.y, S.h[j*4+3], lo); STS32(a1 + 1024, lo);
    }
    __syncwarp();
}

// cosine-similarity epilogue on raw layer-2 accumulators
__device__ __forceinline__ void final_epi(float (&D)[8][4], const float* __restrict__ bias,
                                          const float* __restrict__ tv, float tnorm,
                                          float* __restrict__ outp, int r1, int lane) {
    int c0 = 2 * (lane & 3);
    float n1 = 0.f, s1 = 0.f, n2 = 0.f, s2 = 0.f;
#pragma unroll
    for (int nt = 0; nt < 8; nt++) {
        float b0 = bias[nt*8 + c0], b1 = bias[nt*8 + c0 + 1];
        float t0 = tv[nt*8 + c0],  t1 = tv[nt*8 + c0 + 1];
        float x0 = D[nt][0] + b0, x1 = D[nt][1] + b1;
        float x2 = D[nt][2] + b0, x3 = D[nt][3] + b1;
        n1 = fmaf(x0, t0, fmaf(x1, t1, n1));  s1 = fmaf(x0, x0, fmaf(x1, x1, s1));
        n2 = fmaf(x2, t0, fmaf(x3, t1, n2));  s2 = fmaf(x2, x2, fmaf(x3, x3, s2));
    }
    n1 += __shfl_xor_sync(~0u, n1, 1); n1 += __shfl_xor_sync(~0u, n1, 2);
    s1 += __shfl_xor_sync(~0u, s1, 1); s1 += __shfl_xor_sync(~0u, s1, 2);
    n2 += __shfl_xor_sync(~0u, n2, 1); n2 += __shfl_xor_sync(~0u, n2, 2);
    s2 += __shfl_xor_sync(~0u, s2, 1); s2 += __shfl_xor_sync(~0u, s2, 2);
    if ((lane & 3) == 0) {
        float dn = fmaxf(tnorm, 1e-8f);
        outp[r1]     = n1 / (fmaxf(sqrtf(s1), 1e-8f) * dn) * 10.0f;
        outp[r1 + 8] = n2 / (fmaxf(sqrtf(s2), 1e-8f) * dn) * 10.0f;
    }
}

// ---------------- main kernel ----------------
__global__ void __launch_bounds__(NT, 1) logicnet_mma(
    const int* __restrict__ seq, const int* __restrict__ post, const int* __restrict__ negt,
    const float* __restrict__ item, const float* __restrict__ tvec,
    const float* __restrict__ nb1, const float* __restrict__ nb2,
    const float* __restrict__ ab1, const float* __restrict__ ab2,
    const float* __restrict__ ob1, const float* __restrict__ ob2,
    float* __restrict__ out, int batch)
{
    extern __shared__ unsigned char sm[];
    {   // stage pre-split, pre-swizzled weights
        const float4* s4 = (const float4*)g_wblob;
        float4* d4 = (float4*)sm;
        for (int i = threadIdx.x; i < WBYTES / 16; i += NT) d4[i] = s4[i];
    }
    float* bias = (float*)(sm + BIAS_OFF);
    if (threadIdx.x < 64) {
        int t = threadIdx.x;
        bias[t]       = nb1[t]; bias[64 + t]  = nb2[t];
        bias[128 + t] = ab1[t]; bias[192 + t] = ab2[t];
        bias[256 + t] = ob1[t]; bias[320 + t] = ob2[t];
        ((float*)(sm + TV_OFF))[t] = tvec[t];
    }
    __syncthreads();

    const int lane = threadIdx.x & 31;
    const int wid  = threadIdx.x >> 5;
    const int wrow = wid * 16;
    if (blockIdx.x * TILE + wrow >= batch) return;   // tail-CTA inactive warps

    const uint32_t sb = smem_u32(sm);
    const float* tv = (const float*)(sm + TV_OFF);
    const int bn   = (lane & 7) + ((lane >> 4) << 3);
    const int hk8  = (lane >> 3) & 1;
    const int hk16 = lane >> 4;
    const int rn7  = lane & 7;
    const int g7   = (lane >> 2) & 7;
    const int r1 = blockIdx.x * TILE + wrow + (lane >> 2);
    const int r2 = r1 + 8;

    // act-lo smem addressing (swizzled 128B rows, warp-private 16-row region)
    const uint32_t rdB = sb + ACT_OFF + (uint32_t)((wrow + (lane & 15)) * 128);
    const uint32_t wrB = sb + ACT_OFF + (uint32_t)((wrow + (lane >> 2)) * 128 + ((lane & 3) << 2));
    const uint32_t rdP0 = rdB,            rdP1 = rdB + ABUF,  rdP2 = rdB + 2*ABUF;
    const uint32_t wrP0 = wrB,            wrP1 = wrB + ABUF,  wrP2 = wrB + 2*ABUF;

    float tn = tv[lane] * tv[lane] + tv[lane + 32] * tv[lane + 32];
#pragma unroll
    for (int m = 16; m; m >>= 1) tn += __shfl_xor_sync(~0u, tn, m);
    const float tnorm = sqrtf(tn);

    Slot S0, S1, S2, H;
    float D[8][4];

    gather(S0, wrP0, g7, item, seq[r1*5 + 0], seq[r2*5 + 0], lane);   // e0 -> S0/P0
    gather(S1, wrP1, g7, item, seq[r1*5 + 1], seq[r2*5 + 1], lane);   // e1 -> S1/P1
    // n1 = NOT(e1) -> S1/P1
    mlp(D, H, S1, nullptr, rdP1, 0,    rdP1, wrP1, sb, NW1H, NW1L, RS64,  bias+0,   NW2H, NW2L, bn, hk8, hk16, rn7, g7, lane);
    epi_slot(D, bias + 64, false, S1, wrP1, g7, lane);
    // i5 = AND(e0, n1) -> S0/P0
    mlp(D, H, S0, &S1,     rdP0, rdP1, rdP0, wrP0, sb, AW1H, AW1L, RS128, bias+128, AW2H, AW2L, bn, hk8, hk16, rn7, g7, lane);
    epi_slot(D, bias + 192, false, S0, wrP0, g7, lane);
    gather(S1, wrP1, g7, item, seq[r1*5 + 2], seq[r2*5 + 2], lane);   // e2 -> S1/P1
    gather(S2, wrP2, g7, item, seq[r1*5 + 3], seq[r2*5 + 3], lane);   // e3 -> S2/P2
    // i6 = OR(e2, e3) -> S1/P1
    mlp(D, H, S1, &S2,     rdP1, rdP2, rdP1, wrP1, sb, OW1H, OW1L, RS128, bias+256, OW2H, OW2L, bn, hk8, hk16, rn7, g7, lane);
    epi_slot(D, bias + 320, false, S1, wrP1, g7, lane);
    // i7 = AND(i5, i6) -> S0/P0
    mlp(D, H, S0, &S1,     rdP0, rdP1, rdP0, wrP0, sb, AW1H, AW1L, RS128, bias+128, AW2H, AW2L, bn, hk8, hk16, rn7, g7, lane);
    epi_slot(D, bias + 192, false, S0, wrP0, g7, lane);
    // n7 = NOT(i7) -> S1/P1
    mlp(D, H, S0, nullptr, rdP0, 0,    rdP1, wrP1, sb, NW1H, NW1L, RS64,  bias+0,   NW2H, NW2L, bn, hk8, hk16, rn7, g7, lane);
    epi_slot(D, bias + 64, false, S1, wrP1, g7, lane);
    gather(S2, wrP2, g7, item, seq[r1*5 + 4], seq[r2*5 + 4], lane);   // e4 -> S2/P2
    // i8 = OR(n7, e4) -> S0/P0
    mlp(D, H, S1, &S2,     rdP1, rdP2, rdP0, wrP0, sb, OW1H, OW1L, RS128, bias+256, OW2H, OW2L, bn, hk8, hk16, rn7, g7, lane);
    epi_slot(D, bias + 320, false, S0, wrP0, g7, lane);
    // enc_not = NOT(i8) -> S1/P1
    mlp(D, H, S0, nullptr, rdP0, 0,    rdP1, wrP1, sb, NW1H, NW1L, RS64,  bias+0,   NW2H, NW2L, bn, hk8, hk16, rn7, g7, lane);
    epi_slot(D, bias + 64, false, S1, wrP1, g7, lane);
    gather(S2, wrP2, g7, item, post[r1], post[r2], lane);             // pos_e -> S2/P2
    // encoded_pos = OR(enc_not, pos_e)   (H uses free buffer P0)
    mlp(D, H, S1, &S2,     rdP1, rdP2, rdP0, wrP0, sb, OW1H, OW1L, RS128, bias+256, OW2H, OW2L, bn, hk8, hk16, rn7, g7, lane);
    final_epi(D, bias + 320, tv, tnorm, out, r1, lane);
    gather(S2, wrP2, g7, item, negt[r1], negt[r2], lane);             // neg_e -> S2/P2
    // encoded_neg = OR(enc_not, neg_e)
    mlp(D, H, S1, &S2,     rdP1, rdP2, rdP0, wrP0, sb, OW1H, OW1L, RS128, bias+256, OW2H, OW2L, bn, hk8, hk16, rn7, g7, lane);
    final_epi(D, bias + 320, tv, tnorm, out + batch, r1, lane);
}

extern "C" void kernel_launch(void* const* d_in, const int* in_sizes, int n_in,
                              void* d_out, int out_size) {
    const int*   seq   = (const int*)  d_in[0];
    const int*   pos_t = (const int*)  d_in[1];
    const int*   neg_t = (const int*)  d_in[2];
    const float* item  = (const float*)d_in[3];
    const float* tvec  = (const float*)d_in[4];
    const float* nW1 = (const float*)d_in[5];
    const float* nb1 = (const float*)d_in[6];
    const float* nW2 = (const float*)d_in[7];
    const float* nb2 = (const float*)d_in[8];
    const float* aW1 = (const float*)d_in[9];
    const float* ab1 = (const float*)d_in[10];
    const float* aW2 = (const float*)d_in[11];
    const float* ab2 = (const float*)d_in[12];
    const float* oW1 = (const float*)d_in[13];
    const float* ob1 = (const float*)d_in[14];
    const float* oW2 = (const float*)d_in[15];
    const float* ob2 = (const float*)d_in[16];
    float* out = (float*)d_out;

    int batch = in_sizes[1];
    convert_weights<<<128, 256>>>(nW1, nW2, aW1, aW2, oW1, oW2);

    int grid = (batch + TILE - 1) / TILE;
    cudaFuncSetAttribute(logicnet_mma, cudaFuncAttributeMaxDynamicSharedMemorySize, SMEM_REQ);
    logicnet_mma<<<grid, NT, SMEM_REQ>>>(
        seq, pos_t, neg_t, item, tvec,
        nb1, nb2, ab1, ab2, ob1, ob2, out, batch);
}